// round 10
// baseline (speedup 1.0000x reference)
#include <cuda_runtime.h>
#include <math.h>

// Fused Linear(64->3) + F.normalize + cosine_similarity + acos(deg) + nan->0.
//
// R9 change vs R8: software pipeline. Next iteration's 4 LDG.128s are issued
// BEFORE the current iteration's FMA/butterfly/epilogue, so the memory system
// stays fed during the ~150-cycle compute phase (effective MLP ~8 vs 4).
// R8 profile: DRAM 70.7% with L1/issue/occ all slack => pure latency/duty-
// cycle limitation; prefetch attacks exactly that.

#define EPS 1e-8f
#define RAD2DEG 57.2957795130823208768f  // 180/pi

__global__ __launch_bounds__(256)
void net_kernel(const float* __restrict__ data,   // [N, 64]
                const float* __restrict__ lab,    // [N, 3]
                const float* __restrict__ W,      // [64, 3]
                const float* __restrict__ b,      // [3]
                float* __restrict__ out,          // [N]
                int N, int n_pair)
{
    const int gtid = blockIdx.x * blockDim.x + threadIdx.x;
    const int oct  = gtid >> 3;   // octet id = row-pair index
    const int sub  = gtid & 7;

    // ---- W via 6 vector loads; thread's k-set: {4sub..4sub+3, 32+4sub..+3} ----
    const float4* W4 = reinterpret_cast<const float4*>(W);
    const float4 wa0 = __ldg(W4 + 3 * sub + 0);
    const float4 wa1 = __ldg(W4 + 3 * sub + 1);
    const float4 wa2 = __ldg(W4 + 3 * sub + 2);
    const float4 wb0 = __ldg(W4 + 24 + 3 * sub + 0);
    const float4 wb1 = __ldg(W4 + 24 + 3 * sub + 1);
    const float4 wb2 = __ldg(W4 + 24 + 3 * sub + 2);

    float w0[8], w1[8], w2[8];
    w0[0]=wa0.x; w1[0]=wa0.y; w2[0]=wa0.z;   // k = 4sub+0
    w0[1]=wa0.w; w1[1]=wa1.x; w2[1]=wa1.y;   // k = 4sub+1
    w0[2]=wa1.z; w1[2]=wa1.w; w2[2]=wa2.x;   // k = 4sub+2
    w0[3]=wa2.y; w1[3]=wa2.z; w2[3]=wa2.w;   // k = 4sub+3
    w0[4]=wb0.x; w1[4]=wb0.y; w2[4]=wb0.z;   // k = 32+4sub+0
    w0[5]=wb0.w; w1[5]=wb1.x; w2[5]=wb1.y;   // k = 32+4sub+1
    w0[6]=wb1.z; w1[6]=wb1.w; w2[6]=wb2.x;   // k = 32+4sub+2
    w0[7]=wb2.y; w1[7]=wb2.z; w2[7]=wb2.w;   // k = 32+4sub+3

    const float bb0 = __ldg(b + 0);
    const float bb1 = __ldg(b + 1);
    const float bb2 = __ldg(b + 2);

    const int last = N - 1;

    // ---- prologue: load pair `oct` ----
    int p = oct;
    {
        const int cA0 = min(2 * p,     last);
        const int cB0 = min(2 * p + 1, last);
        const float4* dA = reinterpret_cast<const float4*>(data + (size_t)cA0 * 64);
        const float4* dB = reinterpret_cast<const float4*>(data + (size_t)cB0 * 64);
        float4 va0 = __ldg(dA + sub);
        float4 va1 = __ldg(dA + sub + 8);
        float4 vb0 = __ldg(dB + sub);
        float4 vb1 = __ldg(dB + sub + 8);

        while (__any_sync(0xFFFFFFFFu, 2 * p < N)) {
            const int pn = p + n_pair;
            const bool have_next = __any_sync(0xFFFFFFFFu, 2 * pn < N);

            // ---- prefetch next pair (clamped addresses, warp-uniform guard) ----
            float4 na0, na1, nb0, nb1;
            if (have_next) {
                const int cAn = min(2 * pn,     last);
                const int cBn = min(2 * pn + 1, last);
                const float4* dAn = reinterpret_cast<const float4*>(data + (size_t)cAn * 64);
                const float4* dBn = reinterpret_cast<const float4*>(data + (size_t)cBn * 64);
                na0 = __ldg(dAn + sub);
                na1 = __ldg(dAn + sub + 8);
                nb0 = __ldg(dBn + sub);
                nb1 = __ldg(dBn + sub + 8);
            }

            // ---- consume current pair ----
            float sA0 = 0.f, sA1 = 0.f, sA2 = 0.f;
            float sB0 = 0.f, sB1 = 0.f, sB2 = 0.f;
            const float xA[8] = { va0.x, va0.y, va0.z, va0.w, va1.x, va1.y, va1.z, va1.w };
            const float xB[8] = { vb0.x, vb0.y, vb0.z, vb0.w, vb1.x, vb1.y, vb1.z, vb1.w };
#pragma unroll
            for (int j = 0; j < 8; ++j) {
                sA0 = fmaf(xA[j], w0[j], sA0);
                sA1 = fmaf(xA[j], w1[j], sA1);
                sA2 = fmaf(xA[j], w2[j], sA2);
                sB0 = fmaf(xB[j], w0[j], sB0);
                sB1 = fmaf(xB[j], w1[j], sB1);
                sB2 = fmaf(xB[j], w2[j], sB2);
            }

            // octet butterfly (xor 4/2/1 stays in the 8-lane group), 6 chains
#pragma unroll
            for (int m = 4; m >= 1; m >>= 1) {
                sA0 += __shfl_xor_sync(0xFFFFFFFFu, sA0, m);
                sA1 += __shfl_xor_sync(0xFFFFFFFFu, sA1, m);
                sA2 += __shfl_xor_sync(0xFFFFFFFFu, sA2, m);
                sB0 += __shfl_xor_sync(0xFFFFFFFFu, sB0, m);
                sB1 += __shfl_xor_sync(0xFFFFFFFFu, sB1, m);
                sB2 += __shfl_xor_sync(0xFFFFFFFFu, sB2, m);
            }

            // lane 0 finishes row 2p, lane 1 row 2p+1
            if (sub < 2) {
                const int r = 2 * p + sub;
                if (r < N) {
                    float p0 = (sub ? sB0 : sA0) + bb0;
                    float p1 = (sub ? sB1 : sA1) + bb1;
                    float p2 = (sub ? sB2 : sA2) + bb2;

                    const float* lr = lab + (size_t)r * 3;
                    const float l0 = __ldg(lr + 0);
                    const float l1 = __ldg(lr + 1);
                    const float l2 = __ldg(lr + 2);

                    // F.normalize(pred): pred / max(||pred||, eps)
                    const float pn2  = fmaf(p0, p0, fmaf(p1, p1, p2 * p2));
                    const float pnrm = sqrtf(pn2);
                    const float inv  = 1.0f / fmaxf(pnrm, EPS);

                    // cosine_similarity(pred_n, lab)
                    const float dotraw = fmaf(p0, l0, fmaf(p1, l1, p2 * l2));
                    const float dot    = dotraw * inv;
                    const float na     = fmaxf(pnrm * inv, EPS);
                    const float ln2    = fmaf(l0, l0, fmaf(l1, l1, l2 * l2));
                    const float nb     = fmaxf(sqrtf(ln2), EPS);

                    const float cosv = dot / (na * nb);
                    float loss = acosf(cosv) * RAD2DEG;
                    if (isnan(loss)) loss = 0.0f;

                    out[r] = loss;
                }
            }

            // rotate buffers
            p = pn;
            va0 = na0; va1 = na1; vb0 = nb0; vb1 = nb1;
        }
    }
}

extern "C" void kernel_launch(void* const* d_in, const int* in_sizes, int n_in,
                              void* d_out, int out_size)
{
    const float* data = (const float*)d_in[0];  // [N, 64]
    const float* lab  = (const float*)d_in[1];  // [N, 3]
    const float* W    = (const float*)d_in[2];  // [64, 3]
    const float* b    = (const float*)d_in[3];  // [3]
    float* out        = (float*)d_out;          // [N]

    const int N = out_size;

    // ~4 pair-iterations per octet (8 rows/octet) — proven grid shape (7813 blocks)
    const int threads        = 256;
    const int octs_per_block = threads / 8;                  // 32
    const int pairs          = (N + 1) / 2;
    const int iters          = 4;
    const int blocks = (pairs + octs_per_block * iters - 1) / (octs_per_block * iters);
    const int n_pair = blocks * octs_per_block;

    net_kernel<<<blocks, threads>>>(data, lab, W, b, out, N, n_pair);
}

// round 11
// speedup vs baseline: 1.4829x; 1.4829x over previous
#include <cuda_runtime.h>
#include <math.h>

// Fused Linear(64->3) + F.normalize + cosine_similarity + acos(deg) + nan->0.
//
// R10 vs R8 (best=96.8us, DRAM 70.7%): front-batched QUAD rows per octet per
// iteration. 8 independent line-aligned LDG.128 issued back-to-back (MLP=8,
// 4KB/warp in flight vs 2KB) -- raises the memory duty cycle without the
// loop-carried register rotation that sank R9 (alu-pipe MOV storm, occ 35%).
// 128-thread blocks for finer register-file packing at ~90 regs.

#define EPS 1e-8f
#define RAD2DEG 57.2957795130823208768f  // 180/pi

__global__ __launch_bounds__(128)
void net_kernel(const float* __restrict__ data,   // [N, 64]
                const float* __restrict__ lab,    // [N, 3]
                const float* __restrict__ W,      // [64, 3]
                const float* __restrict__ b,      // [3]
                float* __restrict__ out,          // [N]
                int N, int n_quad)
{
    const int gtid = blockIdx.x * blockDim.x + threadIdx.x;
    const int oct  = gtid >> 3;   // octet id = row-quad index
    const int sub  = gtid & 7;

    // ---- W via 6 vector loads; thread's k-set: {4sub..4sub+3, 32+4sub..+3} ----
    const float4* W4 = reinterpret_cast<const float4*>(W);
    const float4 wa0 = __ldg(W4 + 3 * sub + 0);
    const float4 wa1 = __ldg(W4 + 3 * sub + 1);
    const float4 wa2 = __ldg(W4 + 3 * sub + 2);
    const float4 wb0 = __ldg(W4 + 24 + 3 * sub + 0);
    const float4 wb1 = __ldg(W4 + 24 + 3 * sub + 1);
    const float4 wb2 = __ldg(W4 + 24 + 3 * sub + 2);

    float w0[8], w1[8], w2[8];
    w0[0]=wa0.x; w1[0]=wa0.y; w2[0]=wa0.z;   // k = 4sub+0
    w0[1]=wa0.w; w1[1]=wa1.x; w2[1]=wa1.y;   // k = 4sub+1
    w0[2]=wa1.z; w1[2]=wa1.w; w2[2]=wa2.x;   // k = 4sub+2
    w0[3]=wa2.y; w1[3]=wa2.z; w2[3]=wa2.w;   // k = 4sub+3
    w0[4]=wb0.x; w1[4]=wb0.y; w2[4]=wb0.z;   // k = 32+4sub+0
    w0[5]=wb0.w; w1[5]=wb1.x; w2[5]=wb1.y;   // k = 32+4sub+1
    w0[6]=wb1.z; w1[6]=wb1.w; w2[6]=wb2.x;   // k = 32+4sub+2
    w0[7]=wb2.y; w1[7]=wb2.z; w2[7]=wb2.w;   // k = 32+4sub+3

    const float bb0 = __ldg(b + 0);
    const float bb1 = __ldg(b + 1);
    const float bb2 = __ldg(b + 2);

    const int last = N - 1;

    // Grid-stride over row QUADS. Warp (4 octets) covers 16 consecutive rows;
    // each LDG.128 instruction covers 4 full 128B lines (wavefront minimum).
#pragma unroll 1
    for (int q = oct; __any_sync(0xFFFFFFFFu, 4 * q < N); q += n_quad) {
        const int r0 = 4 * q;
        const int c0 = min(r0,     last);
        const int c1 = min(r0 + 1, last);
        const int c2 = min(r0 + 2, last);
        const int c3 = min(r0 + 3, last);

        const float4* d0 = reinterpret_cast<const float4*>(data + (size_t)c0 * 64);
        const float4* d1 = reinterpret_cast<const float4*>(data + (size_t)c1 * 64);
        const float4* d2 = reinterpret_cast<const float4*>(data + (size_t)c2 * 64);
        const float4* d3 = reinterpret_cast<const float4*>(data + (size_t)c3 * 64);

        // 8 independent LDG.128 issued back-to-back (MLP=8)
        const float4 v00 = __ldg(d0 + sub);
        const float4 v01 = __ldg(d0 + sub + 8);
        const float4 v10 = __ldg(d1 + sub);
        const float4 v11 = __ldg(d1 + sub + 8);
        const float4 v20 = __ldg(d2 + sub);
        const float4 v21 = __ldg(d2 + sub + 8);
        const float4 v30 = __ldg(d3 + sub);
        const float4 v31 = __ldg(d3 + sub + 8);

        float s00=0.f, s01=0.f, s02=0.f;
        float s10=0.f, s11=0.f, s12=0.f;
        float s20=0.f, s21=0.f, s22=0.f;
        float s30=0.f, s31=0.f, s32=0.f;

        const float x0[8] = { v00.x, v00.y, v00.z, v00.w, v01.x, v01.y, v01.z, v01.w };
        const float x1[8] = { v10.x, v10.y, v10.z, v10.w, v11.x, v11.y, v11.z, v11.w };
        const float x2[8] = { v20.x, v20.y, v20.z, v20.w, v21.x, v21.y, v21.z, v21.w };
        const float x3[8] = { v30.x, v30.y, v30.z, v30.w, v31.x, v31.y, v31.z, v31.w };
#pragma unroll
        for (int j = 0; j < 8; ++j) {
            s00 = fmaf(x0[j], w0[j], s00);
            s01 = fmaf(x0[j], w1[j], s01);
            s02 = fmaf(x0[j], w2[j], s02);
            s10 = fmaf(x1[j], w0[j], s10);
            s11 = fmaf(x1[j], w1[j], s11);
            s12 = fmaf(x1[j], w2[j], s12);
            s20 = fmaf(x2[j], w0[j], s20);
            s21 = fmaf(x2[j], w1[j], s21);
            s22 = fmaf(x2[j], w2[j], s22);
            s30 = fmaf(x3[j], w0[j], s30);
            s31 = fmaf(x3[j], w1[j], s31);
            s32 = fmaf(x3[j], w2[j], s32);
        }

        // 12 independent butterfly chains (xor 4/2/1 stays in the 8-lane group)
#pragma unroll
        for (int m = 4; m >= 1; m >>= 1) {
            s00 += __shfl_xor_sync(0xFFFFFFFFu, s00, m);
            s01 += __shfl_xor_sync(0xFFFFFFFFu, s01, m);
            s02 += __shfl_xor_sync(0xFFFFFFFFu, s02, m);
            s10 += __shfl_xor_sync(0xFFFFFFFFu, s10, m);
            s11 += __shfl_xor_sync(0xFFFFFFFFu, s11, m);
            s12 += __shfl_xor_sync(0xFFFFFFFFu, s12, m);
            s20 += __shfl_xor_sync(0xFFFFFFFFu, s20, m);
            s21 += __shfl_xor_sync(0xFFFFFFFFu, s21, m);
            s22 += __shfl_xor_sync(0xFFFFFFFFu, s22, m);
            s30 += __shfl_xor_sync(0xFFFFFFFFu, s30, m);
            s31 += __shfl_xor_sync(0xFFFFFFFFu, s31, m);
            s32 += __shfl_xor_sync(0xFFFFFFFFu, s32, m);
        }

        // Sums live in all 8 lanes: lane j (j<4) finishes row r0+j.
        if (sub < 4) {
            const int r = r0 + sub;
            if (r < N) {
                float p0 = (sub == 0 ? s00 : sub == 1 ? s10 : sub == 2 ? s20 : s30) + bb0;
                float p1 = (sub == 0 ? s01 : sub == 1 ? s11 : sub == 2 ? s21 : s31) + bb1;
                float p2 = (sub == 0 ? s02 : sub == 1 ? s12 : sub == 2 ? s22 : s32) + bb2;

                const float* lr = lab + (size_t)r * 3;
                const float l0 = __ldg(lr + 0);
                const float l1 = __ldg(lr + 1);
                const float l2 = __ldg(lr + 2);

                // F.normalize(pred): pred / max(||pred||, eps)
                const float pn2  = fmaf(p0, p0, fmaf(p1, p1, p2 * p2));
                const float pnrm = sqrtf(pn2);
                const float inv  = 1.0f / fmaxf(pnrm, EPS);

                // cosine_similarity(pred_n, lab)
                const float dotraw = fmaf(p0, l0, fmaf(p1, l1, p2 * l2));
                const float dot    = dotraw * inv;
                const float na     = fmaxf(pnrm * inv, EPS);
                const float ln2    = fmaf(l0, l0, fmaf(l1, l1, l2 * l2));
                const float nb     = fmaxf(sqrtf(ln2), EPS);

                const float cosv = dot / (na * nb);
                float loss = acosf(cosv) * RAD2DEG;
                if (isnan(loss)) loss = 0.0f;

                out[r] = loss;
            }
        }
    }
}

extern "C" void kernel_launch(void* const* d_in, const int* in_sizes, int n_in,
                              void* d_out, int out_size)
{
    const float* data = (const float*)d_in[0];  // [N, 64]
    const float* lab  = (const float*)d_in[1];  // [N, 3]
    const float* W    = (const float*)d_in[2];  // [64, 3]
    const float* b    = (const float*)d_in[3];  // [3]
    float* out        = (float*)d_out;          // [N]

    const int N = out_size;

    // 128-thread blocks, 16 octets/block, 4 rows/octet/iter, 2 iterations
    // -> 128 rows per block -> 15625 blocks for N=2M.
    const int threads        = 128;
    const int octs_per_block = threads / 8;                  // 16
    const int quads          = (N + 3) / 4;
    const int iters          = 2;
    const int blocks = (quads + octs_per_block * iters - 1) / (octs_per_block * iters);
    const int n_quad = blocks * octs_per_block;

    net_kernel<<<blocks, threads>>>(data, lab, W, b, out, N, n_quad);
}

// round 16
// speedup vs baseline: 1.6945x; 1.1427x over previous
#include <cuda_runtime.h>
#include <math.h>
#include <stdint.h>

// Fused Linear(64->3) + F.normalize + cosine_similarity + acos(deg) + nan->0.
//
// R11 experiment: R8/R10 both pinned at ~5.6 TB/s (DRAM 70.7%/71.1%) despite
// 2x different MLP/occupancy => LDG-path ceiling, not latency. B300 docs: the
// ~6300 B/cyc LTS cap is PATH-INDEPENDENT (TMA == LDG.cv). This round moves
// the stream to cp.async.bulk (UBLKCP) -> SMEM, double-buffered mbarrier
// pipeline, compute from SMEM with the proven R10 octet/butterfly structure.

#define EPS 1e-8f
#define RAD2DEG 57.2957795130823208768f  // 180/pi

#define TILE_ROWS   256
#define NTHREADS    512                   // 64 octets = 64 quads per tile
#define GRID_BLKS   296
#define DATA_BYTES  (TILE_ROWS * 256)     // 65536
#define LAB_BYTES   (TILE_ROWS * 12)      // 3072
#define STAGE_BYTES (DATA_BYTES + LAB_BYTES)
#define SMEM_DATA0  128                   // barriers live in [0,128)
#define SMEM_TOTAL  (128 + 2 * STAGE_BYTES)

__device__ __forceinline__ uint32_t smem_u32(const void* p) {
    return (uint32_t)__cvta_generic_to_shared(p);
}
__device__ __forceinline__ void mbar_init(uint32_t a, uint32_t cnt) {
    asm volatile("mbarrier.init.shared.b64 [%0], %1;" :: "r"(a), "r"(cnt) : "memory");
}
__device__ __forceinline__ void mbar_expect_tx(uint32_t a, uint32_t bytes) {
    asm volatile("mbarrier.arrive.expect_tx.shared.b64 _, [%0], %1;"
                 :: "r"(a), "r"(bytes) : "memory");
}
__device__ __forceinline__ void mbar_arrive(uint32_t a) {
    asm volatile("mbarrier.arrive.shared.b64 _, [%0];" :: "r"(a) : "memory");
}
__device__ __forceinline__ void mbar_wait(uint32_t a, uint32_t parity) {
    uint32_t done;
    asm volatile(
        "{\n\t.reg .pred P;\n\t"
        "mbarrier.try_wait.parity.acquire.cta.shared::cta.b64 P, [%1], %2;\n\t"
        "selp.b32 %0, 1, 0, P;\n\t}"
        : "=r"(done) : "r"(a), "r"(parity) : "memory");
    while (!done) {
        asm volatile(
            "{\n\t.reg .pred P;\n\t"
            "mbarrier.try_wait.parity.acquire.cta.shared::cta.b64 P, [%1], %2, 0x989680;\n\t"
            "selp.b32 %0, 1, 0, P;\n\t}"
            : "=r"(done) : "r"(a), "r"(parity) : "memory");
    }
}
__device__ __forceinline__ void bulk_copy_g2s(uint32_t dst, const void* src,
                                              uint32_t bytes, uint32_t mbar) {
    asm volatile(
        "cp.async.bulk.shared::cluster.global.mbarrier::complete_tx::bytes "
        "[%0], [%1], %2, [%3];"
        :: "r"(dst), "l"(src), "r"(bytes), "r"(mbar) : "memory");
}

__global__ __launch_bounds__(NTHREADS, 1)
void net_kernel(const float* __restrict__ data,   // [N, 64]
                const float* __restrict__ lab,    // [N, 3]
                const float* __restrict__ W,      // [64, 3]
                const float* __restrict__ b,      // [3]
                float* __restrict__ out,          // [N]
                int N, int n_tiles)
{
    extern __shared__ __align__(128) char smem[];
    const uint32_t sbase = smem_u32(smem);
    // barriers: full(s) at sbase + 32*s, empty(s) at sbase + 32*s + 16
    const int tid = threadIdx.x;
    const int oct = tid >> 3;         // 0..63 : quad index within tile
    const int sub = tid & 7;

    if (tid == 0) {
        mbar_init(sbase + 0,       1);          // full0  (tx-based)
        mbar_init(sbase + 16,      NTHREADS);   // empty0 (all threads arrive)
        mbar_init(sbase + 32,      1);          // full1
        mbar_init(sbase + 48,      NTHREADS);   // empty1
    }
    __syncthreads();

    // ---- W/b register setup (identical to R10; L1-resident one-time) ----
    const float4* W4 = reinterpret_cast<const float4*>(W);
    const float4 wa0 = __ldg(W4 + 3 * sub + 0);
    const float4 wa1 = __ldg(W4 + 3 * sub + 1);
    const float4 wa2 = __ldg(W4 + 3 * sub + 2);
    const float4 wb0 = __ldg(W4 + 24 + 3 * sub + 0);
    const float4 wb1 = __ldg(W4 + 24 + 3 * sub + 1);
    const float4 wb2 = __ldg(W4 + 24 + 3 * sub + 2);

    float w0[8], w1[8], w2[8];
    w0[0]=wa0.x; w1[0]=wa0.y; w2[0]=wa0.z;
    w0[1]=wa0.w; w1[1]=wa1.x; w2[1]=wa1.y;
    w0[2]=wa1.z; w1[2]=wa1.w; w2[2]=wa2.x;
    w0[3]=wa2.y; w1[3]=wa2.z; w2[3]=wa2.w;
    w0[4]=wb0.x; w1[4]=wb0.y; w2[4]=wb0.z;
    w0[5]=wb0.w; w1[5]=wb1.x; w2[5]=wb1.y;
    w0[6]=wb1.z; w1[6]=wb1.w; w2[6]=wb2.x;
    w0[7]=wb2.y; w1[7]=wb2.z; w2[7]=wb2.w;

    const float bb0 = __ldg(b + 0);
    const float bb1 = __ldg(b + 1);
    const float bb2 = __ldg(b + 2);

    // My tiles: g, g+GRID, ... (per-block count M)
    const int g = blockIdx.x;
    int M = 0;
    for (int t = g; t < n_tiles; t += GRID_BLKS) ++M;   // small loop, ~26 iters

    // ---- producer helper (thread 0 only) ----
    auto produce = [&](int k) {   // production round k -> stage k&1
        const int   s     = k & 1;
        const uint32_t fullb  = sbase + 32 * s;
        const uint32_t emptyb = sbase + 32 * s + 16;
        const uint32_t ph_e   = 1u ^ ((unsigned)(k >> 1) & 1u);
        mbar_wait(emptyb, ph_e);                        // first use passes
        const long long tile = (long long)g + (long long)k * GRID_BLKS;
        const long long base = tile * TILE_ROWS;
        const int rows  = (int)min((long long)TILE_ROWS, (long long)N - base);
        const uint32_t dby = (uint32_t)rows * 256u;
        const uint32_t lby = (uint32_t)rows * 12u;      // rows%4==0 -> 16B mult
        mbar_expect_tx(fullb, dby + lby);
        const uint32_t ddst = sbase + SMEM_DATA0 + s * STAGE_BYTES;
        const uint32_t ldst = ddst + DATA_BYTES;
        bulk_copy_g2s(ddst, data + base * 64, dby, fullb);
        bulk_copy_g2s(ldst, lab  + base * 3,  lby, fullb);
    };

    // prologue: fill both stages
    if (tid == 0) {
        if (M > 0) produce(0);
        if (M > 1) produce(1);
    }

    for (int m = 0; m < M; ++m) {
        const int s = m & 1;
        const uint32_t fullb  = sbase + 32 * s;
        const uint32_t emptyb = sbase + 32 * s + 16;
        const uint32_t ph_f   = (unsigned)(m >> 1) & 1u;

        mbar_wait(fullb, ph_f);

        const float* sdata = reinterpret_cast<const float*>(smem + SMEM_DATA0 + s * STAGE_BYTES);
        const float* slab  = sdata + DATA_BYTES / 4;

        const long long tile_base = ((long long)g + (long long)m * GRID_BLKS) * TILE_ROWS;
        const int r0l = 4 * oct;   // local quad rows r0l..r0l+3 (always < 256)

        // 8 LDS.128, each octet reads a contiguous 128B chunk -> conflict-free
        const float4* d0 = reinterpret_cast<const float4*>(sdata + (r0l + 0) * 64);
        const float4* d1 = reinterpret_cast<const float4*>(sdata + (r0l + 1) * 64);
        const float4* d2 = reinterpret_cast<const float4*>(sdata + (r0l + 2) * 64);
        const float4* d3 = reinterpret_cast<const float4*>(sdata + (r0l + 3) * 64);
        const float4 v00 = d0[sub], v01 = d0[sub + 8];
        const float4 v10 = d1[sub], v11 = d1[sub + 8];
        const float4 v20 = d2[sub], v21 = d2[sub + 8];
        const float4 v30 = d3[sub], v31 = d3[sub + 8];

        float s00=0.f,s01=0.f,s02=0.f, s10=0.f,s11=0.f,s12=0.f;
        float s20=0.f,s21=0.f,s22=0.f, s30=0.f,s31=0.f,s32=0.f;
        const float x0[8] = { v00.x,v00.y,v00.z,v00.w, v01.x,v01.y,v01.z,v01.w };
        const float x1[8] = { v10.x,v10.y,v10.z,v10.w, v11.x,v11.y,v11.z,v11.w };
        const float x2[8] = { v20.x,v20.y,v20.z,v20.w, v21.x,v21.y,v21.z,v21.w };
        const float x3[8] = { v30.x,v30.y,v30.z,v30.w, v31.x,v31.y,v31.z,v31.w };
#pragma unroll
        for (int j = 0; j < 8; ++j) {
            s00 = fmaf(x0[j], w0[j], s00); s01 = fmaf(x0[j], w1[j], s01); s02 = fmaf(x0[j], w2[j], s02);
            s10 = fmaf(x1[j], w0[j], s10); s11 = fmaf(x1[j], w1[j], s11); s12 = fmaf(x1[j], w2[j], s12);
            s20 = fmaf(x2[j], w0[j], s20); s21 = fmaf(x2[j], w1[j], s21); s22 = fmaf(x2[j], w2[j], s22);
            s30 = fmaf(x3[j], w0[j], s30); s31 = fmaf(x3[j], w1[j], s31); s32 = fmaf(x3[j], w2[j], s32);
        }
#pragma unroll
        for (int msk = 4; msk >= 1; msk >>= 1) {
            s00 += __shfl_xor_sync(0xFFFFFFFFu, s00, msk);
            s01 += __shfl_xor_sync(0xFFFFFFFFu, s01, msk);
            s02 += __shfl_xor_sync(0xFFFFFFFFu, s02, msk);
            s10 += __shfl_xor_sync(0xFFFFFFFFu, s10, msk);
            s11 += __shfl_xor_sync(0xFFFFFFFFu, s11, msk);
            s12 += __shfl_xor_sync(0xFFFFFFFFu, s12, msk);
            s20 += __shfl_xor_sync(0xFFFFFFFFu, s20, msk);
            s21 += __shfl_xor_sync(0xFFFFFFFFu, s21, msk);
            s22 += __shfl_xor_sync(0xFFFFFFFFu, s22, msk);
            s30 += __shfl_xor_sync(0xFFFFFFFFu, s30, msk);
            s31 += __shfl_xor_sync(0xFFFFFFFFu, s31, msk);
            s32 += __shfl_xor_sync(0xFFFFFFFFu, s32, msk);
        }

        if (sub < 4) {
            const long long r = tile_base + r0l + sub;
            if (r < N) {
                float p0 = (sub==0 ? s00 : sub==1 ? s10 : sub==2 ? s20 : s30) + bb0;
                float p1 = (sub==0 ? s01 : sub==1 ? s11 : sub==2 ? s21 : s31) + bb1;
                float p2 = (sub==0 ? s02 : sub==1 ? s12 : sub==2 ? s22 : s32) + bb2;

                const float* lr = slab + (r0l + sub) * 3;
                const float l0 = lr[0], l1 = lr[1], l2 = lr[2];

                const float pn2  = fmaf(p0, p0, fmaf(p1, p1, p2 * p2));
                const float pnrm = sqrtf(pn2);
                const float inv  = 1.0f / fmaxf(pnrm, EPS);
                const float dotr = fmaf(p0, l0, fmaf(p1, l1, p2 * l2));
                const float dotv = dotr * inv;
                const float na   = fmaxf(pnrm * inv, EPS);
                const float ln2  = fmaf(l0, l0, fmaf(l1, l1, l2 * l2));
                const float nb   = fmaxf(sqrtf(ln2), EPS);

                const float cosv = dotv / (na * nb);
                float loss = acosf(cosv) * RAD2DEG;
                if (isnan(loss)) loss = 0.0f;
                out[r] = loss;
            }
        }

        // done reading stage s (LDS results consumed by FMAs above)
        mbar_arrive(emptyb);

        if (tid == 0 && (m + 2) < M) produce(m + 2);
    }
}

extern "C" void kernel_launch(void* const* d_in, const int* in_sizes, int n_in,
                              void* d_out, int out_size)
{
    const float* data = (const float*)d_in[0];  // [N, 64]
    const float* lab  = (const float*)d_in[1];  // [N, 3]
    const float* W    = (const float*)d_in[2];  // [64, 3]
    const float* b    = (const float*)d_in[3];  // [3]
    float* out        = (float*)d_out;          // [N]

    const int N       = out_size;
    const int n_tiles = (N + TILE_ROWS - 1) / TILE_ROWS;

    static bool attr_set = false;
    if (!attr_set) {
        cudaFuncSetAttribute(net_kernel,
                             cudaFuncAttributeMaxDynamicSharedMemorySize, SMEM_TOTAL);
        attr_set = true;
    }

    net_kernel<<<GRID_BLKS, NTHREADS, SMEM_TOTAL>>>(data, lab, W, b, out, N, n_tiles);
}

// round 17
// speedup vs baseline: 1.7273x; 1.0193x over previous
#include <cuda_runtime.h>
#include <math.h>
#include <stdint.h>

// Fused Linear(64->3) + F.normalize + cosine_similarity + acos(deg) + nan->0.
//
// R16 vs R11 (86.1us, DRAM 80.1%): pipeline restructure to close the copy-
// engine bubbles.
//  - 3-stage pipeline: produce(m+2) is issued at the TOP of iteration m into
//    a stage emptied at the end of m-1 (empty-wait passes instantly), so the
//    bulk-copy engine runs during the entire compute phase.
//  - Persistent grid=148 (one wave) instead of 296 (two waves).
//  - Empty barrier: one arrive per warp (count=16) after __syncwarp, instead
//    of 512 contended arrives (~500 cyc/tile of smem-atomic serialization).

#define EPS 1e-8f
#define RAD2DEG 57.2957795130823208768f  // 180/pi

#define TILE_ROWS   256
#define NTHREADS    512                   // 64 octets = 64 quads per tile
#define NWARPS      (NTHREADS / 32)       // 16
#define GRID_BLKS   148
#define NSTAGES     3
#define DATA_BYTES  (TILE_ROWS * 256)     // 65536
#define LAB_BYTES   (TILE_ROWS * 12)      // 3072
#define STAGE_BYTES (DATA_BYTES + LAB_BYTES)
#define SMEM_DATA0  128                   // barriers live in [0,128)
#define SMEM_TOTAL  (128 + NSTAGES * STAGE_BYTES)

__device__ __forceinline__ uint32_t smem_u32(const void* p) {
    return (uint32_t)__cvta_generic_to_shared(p);
}
__device__ __forceinline__ void mbar_init(uint32_t a, uint32_t cnt) {
    asm volatile("mbarrier.init.shared.b64 [%0], %1;" :: "r"(a), "r"(cnt) : "memory");
}
__device__ __forceinline__ void mbar_expect_tx(uint32_t a, uint32_t bytes) {
    asm volatile("mbarrier.arrive.expect_tx.shared.b64 _, [%0], %1;"
                 :: "r"(a), "r"(bytes) : "memory");
}
__device__ __forceinline__ void mbar_arrive(uint32_t a) {
    asm volatile("mbarrier.arrive.shared.b64 _, [%0];" :: "r"(a) : "memory");
}
__device__ __forceinline__ void mbar_wait(uint32_t a, uint32_t parity) {
    uint32_t done;
    asm volatile(
        "{\n\t.reg .pred P;\n\t"
        "mbarrier.try_wait.parity.acquire.cta.shared::cta.b64 P, [%1], %2;\n\t"
        "selp.b32 %0, 1, 0, P;\n\t}"
        : "=r"(done) : "r"(a), "r"(parity) : "memory");
    while (!done) {
        asm volatile(
            "{\n\t.reg .pred P;\n\t"
            "mbarrier.try_wait.parity.acquire.cta.shared::cta.b64 P, [%1], %2, 0x989680;\n\t"
            "selp.b32 %0, 1, 0, P;\n\t}"
            : "=r"(done) : "r"(a), "r"(parity) : "memory");
    }
}
__device__ __forceinline__ void bulk_copy_g2s(uint32_t dst, const void* src,
                                              uint32_t bytes, uint32_t mbar) {
    asm volatile(
        "cp.async.bulk.shared::cluster.global.mbarrier::complete_tx::bytes "
        "[%0], [%1], %2, [%3];"
        :: "r"(dst), "l"(src), "r"(bytes), "r"(mbar) : "memory");
}

__global__ __launch_bounds__(NTHREADS, 1)
void net_kernel(const float* __restrict__ data,   // [N, 64]
                const float* __restrict__ lab,    // [N, 3]
                const float* __restrict__ W,      // [64, 3]
                const float* __restrict__ b,      // [3]
                float* __restrict__ out,          // [N]
                int N, int n_tiles)
{
    extern __shared__ __align__(128) char smem[];
    const uint32_t sbase = smem_u32(smem);
    // barriers: full(s) at sbase + 32*s, empty(s) at sbase + 32*s + 16
    const int tid = threadIdx.x;
    const int oct = tid >> 3;         // 0..63 : quad index within tile
    const int sub = tid & 7;

    if (tid == 0) {
#pragma unroll
        for (int s = 0; s < NSTAGES; ++s) {
            mbar_init(sbase + 32 * s,      1);        // full: tx-based
            mbar_init(sbase + 32 * s + 16, NWARPS);   // empty: 1 arrive/warp
        }
    }
    __syncthreads();

    // ---- W/b register setup (L1-resident one-time) ----
    const float4* W4 = reinterpret_cast<const float4*>(W);
    const float4 wa0 = __ldg(W4 + 3 * sub + 0);
    const float4 wa1 = __ldg(W4 + 3 * sub + 1);
    const float4 wa2 = __ldg(W4 + 3 * sub + 2);
    const float4 wb0 = __ldg(W4 + 24 + 3 * sub + 0);
    const float4 wb1 = __ldg(W4 + 24 + 3 * sub + 1);
    const float4 wb2 = __ldg(W4 + 24 + 3 * sub + 2);

    float w0[8], w1[8], w2[8];
    w0[0]=wa0.x; w1[0]=wa0.y; w2[0]=wa0.z;
    w0[1]=wa0.w; w1[1]=wa1.x; w2[1]=wa1.y;
    w0[2]=wa1.z; w1[2]=wa1.w; w2[2]=wa2.x;
    w0[3]=wa2.y; w1[3]=wa2.z; w2[3]=wa2.w;
    w0[4]=wb0.x; w1[4]=wb0.y; w2[4]=wb0.z;
    w0[5]=wb0.w; w1[5]=wb1.x; w2[5]=wb1.y;
    w0[6]=wb1.z; w1[6]=wb1.w; w2[6]=wb2.x;
    w0[7]=wb2.y; w1[7]=wb2.z; w2[7]=wb2.w;

    const float bb0 = __ldg(b + 0);
    const float bb1 = __ldg(b + 1);
    const float bb2 = __ldg(b + 2);

    const int g = blockIdx.x;
    int M = 0;
    for (int t = g; t < n_tiles; t += GRID_BLKS) ++M;

    // ---- producer cursor (thread 0 only): stage + empty-phase, mod-3 ----
    int pr_stage = 0, pr_phase = 1;    // empty barrier: first wait must pass
    auto produce = [&](int k) {        // k-th production round (sequential)
        const uint32_t fullb  = sbase + 32 * pr_stage;
        const uint32_t emptyb = sbase + 32 * pr_stage + 16;
        mbar_wait(emptyb, (uint32_t)pr_phase);
        const long long tile = (long long)g + (long long)k * GRID_BLKS;
        const long long base = tile * TILE_ROWS;
        const int rows = (int)min((long long)TILE_ROWS, (long long)N - base);
        const uint32_t dby = (uint32_t)rows * 256u;
        const uint32_t lby = (uint32_t)rows * 12u;     // rows%4==0 -> 16B mult
        mbar_expect_tx(fullb, dby + lby);
        const uint32_t ddst = sbase + SMEM_DATA0 + pr_stage * STAGE_BYTES;
        bulk_copy_g2s(ddst,              data + base * 64, dby, fullb);
        bulk_copy_g2s(ddst + DATA_BYTES, lab  + base * 3,  lby, fullb);
        if (++pr_stage == NSTAGES) { pr_stage = 0; pr_phase ^= 1; }
    };

    // prologue: fill stages 0 and 1
    if (tid == 0) {
        if (M > 0) produce(0);
        if (M > 1) produce(1);
    }

    // ---- consumer cursor ----
    int cs_stage = 0, cs_phase = 0;

    for (int m = 0; m < M; ++m) {
        const int s = cs_stage;
        const uint32_t fullb  = sbase + 32 * s;
        const uint32_t emptyb = sbase + 32 * s + 16;

        mbar_wait(fullb, (uint32_t)cs_phase);

        // Issue the NEXT copy immediately: its target stage was emptied at the
        // end of iteration m-1, so the producer's empty-wait passes instantly
        // and the copy engine overlaps this tile's entire compute phase.
        if (tid == 0 && (m + 2) < M) produce(m + 2);

        const float* sdata = reinterpret_cast<const float*>(smem + SMEM_DATA0 + s * STAGE_BYTES);
        const float* slab  = sdata + DATA_BYTES / 4;

        const long long tile_base = ((long long)g + (long long)m * GRID_BLKS) * TILE_ROWS;
        const int r0l = 4 * oct;

        // 8 LDS.128; each octet reads contiguous 128B chunks -> conflict-free
        const float4* d0 = reinterpret_cast<const float4*>(sdata + (r0l + 0) * 64);
        const float4* d1 = reinterpret_cast<const float4*>(sdata + (r0l + 1) * 64);
        const float4* d2 = reinterpret_cast<const float4*>(sdata + (r0l + 2) * 64);
        const float4* d3 = reinterpret_cast<const float4*>(sdata + (r0l + 3) * 64);
        const float4 v00 = d0[sub], v01 = d0[sub + 8];
        const float4 v10 = d1[sub], v11 = d1[sub + 8];
        const float4 v20 = d2[sub], v21 = d2[sub + 8];
        const float4 v30 = d3[sub], v31 = d3[sub + 8];

        float s00=0.f,s01=0.f,s02=0.f, s10=0.f,s11=0.f,s12=0.f;
        float s20=0.f,s21=0.f,s22=0.f, s30=0.f,s31=0.f,s32=0.f;
        const float x0[8] = { v00.x,v00.y,v00.z,v00.w, v01.x,v01.y,v01.z,v01.w };
        const float x1[8] = { v10.x,v10.y,v10.z,v10.w, v11.x,v11.y,v11.z,v11.w };
        const float x2[8] = { v20.x,v20.y,v20.z,v20.w, v21.x,v21.y,v21.z,v21.w };
        const float x3[8] = { v30.x,v30.y,v30.z,v30.w, v31.x,v31.y,v31.z,v31.w };
#pragma unroll
        for (int j = 0; j < 8; ++j) {
            s00 = fmaf(x0[j], w0[j], s00); s01 = fmaf(x0[j], w1[j], s01); s02 = fmaf(x0[j], w2[j], s02);
            s10 = fmaf(x1[j], w0[j], s10); s11 = fmaf(x1[j], w1[j], s11); s12 = fmaf(x1[j], w2[j], s12);
            s20 = fmaf(x2[j], w0[j], s20); s21 = fmaf(x2[j], w1[j], s21); s22 = fmaf(x2[j], w2[j], s22);
            s30 = fmaf(x3[j], w0[j], s30); s31 = fmaf(x3[j], w1[j], s31); s32 = fmaf(x3[j], w2[j], s32);
        }
#pragma unroll
        for (int msk = 4; msk >= 1; msk >>= 1) {
            s00 += __shfl_xor_sync(0xFFFFFFFFu, s00, msk);
            s01 += __shfl_xor_sync(0xFFFFFFFFu, s01, msk);
            s02 += __shfl_xor_sync(0xFFFFFFFFu, s02, msk);
            s10 += __shfl_xor_sync(0xFFFFFFFFu, s10, msk);
            s11 += __shfl_xor_sync(0xFFFFFFFFu, s11, msk);
            s12 += __shfl_xor_sync(0xFFFFFFFFu, s12, msk);
            s20 += __shfl_xor_sync(0xFFFFFFFFu, s20, msk);
            s21 += __shfl_xor_sync(0xFFFFFFFFu, s21, msk);
            s22 += __shfl_xor_sync(0xFFFFFFFFu, s22, msk);
            s30 += __shfl_xor_sync(0xFFFFFFFFu, s30, msk);
            s31 += __shfl_xor_sync(0xFFFFFFFFu, s31, msk);
            s32 += __shfl_xor_sync(0xFFFFFFFFu, s32, msk);
        }

        if (sub < 4) {
            const long long r = tile_base + r0l + sub;
            if (r < N) {
                float p0 = (sub==0 ? s00 : sub==1 ? s10 : sub==2 ? s20 : s30) + bb0;
                float p1 = (sub==0 ? s01 : sub==1 ? s11 : sub==2 ? s21 : s31) + bb1;
                float p2 = (sub==0 ? s02 : sub==1 ? s12 : sub==2 ? s22 : s32) + bb2;

                const float* lr = slab + (r0l + sub) * 3;
                const float l0 = lr[0], l1 = lr[1], l2 = lr[2];

                const float pn2  = fmaf(p0, p0, fmaf(p1, p1, p2 * p2));
                const float pnrm = sqrtf(pn2);
                const float inv  = 1.0f / fmaxf(pnrm, EPS);
                const float dotr = fmaf(p0, l0, fmaf(p1, l1, p2 * l2));
                const float dotv = dotr * inv;
                const float na   = fmaxf(pnrm * inv, EPS);
                const float ln2  = fmaf(l0, l0, fmaf(l1, l1, l2 * l2));
                const float nb   = fmaxf(sqrtf(ln2), EPS);

                const float cosv = dotv / (na * nb);
                float loss = acosf(cosv) * RAD2DEG;
                if (isnan(loss)) loss = 0.0f;
                out[r] = loss;
            }
        }

        // stage s consumed: one arrive per warp (empty count = NWARPS)
        __syncwarp();
        if ((tid & 31) == 0) mbar_arrive(emptyb);

        if (++cs_stage == NSTAGES) { cs_stage = 0; cs_phase ^= 1; }
    }
}

extern "C" void kernel_launch(void* const* d_in, const int* in_sizes, int n_in,
                              void* d_out, int out_size)
{
    const float* data = (const float*)d_in[0];  // [N, 64]
    const float* lab  = (const float*)d_in[1];  // [N, 3]
    const float* W    = (const float*)d_in[2];  // [64, 3]
    const float* b    = (const float*)d_in[3];  // [3]
    float* out        = (float*)d_out;          // [N]

    const int N       = out_size;
    const int n_tiles = (N + TILE_ROWS - 1) / TILE_ROWS;

    static bool attr_set = false;
    if (!attr_set) {
        cudaFuncSetAttribute(net_kernel,
                             cudaFuncAttributeMaxDynamicSharedMemorySize, SMEM_TOTAL);
        attr_set = true;
    }

    net_kernel<<<GRID_BLKS, NTHREADS, SMEM_TOTAL>>>(data, lab, W, b, out, N, n_tiles);
}